// round 8
// baseline (speedup 1.0000x reference)
#include <cuda_runtime.h>

// ---------------------------------------------------------------------------
// NeuralODEFlow: z' = mlp(z), Euler, log_det via finite-difference trace.
// Key identity (mlp is piecewise linear in z):
//   trace_step = dt/H * sum_j (y_new_j - y_old_j)   [the "updated-z bug" term]
//              + dt * m1^T Q m2                      [exact masked Jacobian trace]
// with Q[k,i] = W2[k,i] * (W3@W1)[i,k], m1/m2 = ReLU masks at z_new.
// ---------------------------------------------------------------------------

#define BATCH 1024
#define DIM   64
#define HID   512
#define NSTEP 9
#define HSTEP 1e-5f

// scratch (device globals: allocation-free)
__device__ float g_Q[HID * HID];
__device__ float g_z[BATCH * DIM];
__device__ float g_h1[BATCH * HID];
__device__ float g_h2[BATCH * HID];
__device__ float g_y[2][BATCH * DIM];
__device__ float g_part[BATCH * 8];

// ---------------------------------------------------------------------------
// Q[k,i] = W2[k,i] * sum_j W3[i,j] * W1[j,k];  also zero the log_det output.
// grid: 512 blocks (one per k), 256 threads.
// ---------------------------------------------------------------------------
__global__ __launch_bounds__(256) void k_init(const float* __restrict__ W1,
                                              const float* __restrict__ W2,
                                              const float* __restrict__ W3,
                                              float* __restrict__ out_logdet) {
    int k = blockIdx.x;
    for (int i = threadIdx.x; i < HID; i += blockDim.x) {
        float p = 0.f;
#pragma unroll
        for (int j = 0; j < DIM; ++j)
            p += W3[i * DIM + j] * W1[j * HID + k];
        g_Q[k * HID + i] = W2[k * HID + i] * p;
    }
    if (blockIdx.x == 0) {
        for (int i = threadIdx.x; i < BATCH; i += blockDim.x)
            out_logdet[i] = 0.f;
    }
}

// ---------------------------------------------------------------------------
// K1: z_new = (first ? x : z + dt*y_old);  h1 = relu(z_new @ W1 + b1)
// grid: 64 blocks * 256 threads, 16 rows per block.
// ---------------------------------------------------------------------------
__global__ __launch_bounds__(256) void k1_layer1(const float* __restrict__ xin,
                                                 const float* __restrict__ W1,
                                                 const float* __restrict__ b1,
                                                 float dt, int oldIdx, int first) {
    __shared__ float zs[16 * 64];
    const float* yo = g_y[oldIdx];
    int row0 = blockIdx.x * 16;
    int t = threadIdx.x;

#pragma unroll
    for (int q = 0; q < 4; ++q) {
        int idx = t + 256 * q;               // 0..1023 within block's 16x64
        int g = row0 * DIM + idx;
        float z = first ? xin[g] : (g_z[g] + dt * yo[g]);
        zs[idx] = z;
        g_z[g] = z;
    }
    __syncthreads();

    float acc0[16], acc1[16];
#pragma unroll
    for (int r = 0; r < 16; ++r) { acc0[r] = 0.f; acc1[r] = 0.f; }
    int c0 = t, c1 = t + 256;
#pragma unroll 4
    for (int k = 0; k < 64; ++k) {
        float wa = W1[k * HID + c0];
        float wb = W1[k * HID + c1];
#pragma unroll
        for (int r = 0; r < 16; ++r) {
            float z = zs[r * 64 + k];
            acc0[r] += z * wa;
            acc1[r] += z * wb;
        }
    }
    float ba = b1[c0], bb = b1[c1];
#pragma unroll
    for (int r = 0; r < 16; ++r) {
        g_h1[(row0 + r) * HID + c0] = fmaxf(acc0[r] + ba, 0.f);
        g_h1[(row0 + r) * HID + c1] = fmaxf(acc1[r] + bb, 0.f);
    }
}

// ---------------------------------------------------------------------------
// K2: fused dual GEMM over A = h1 [1024x512]:
//   u2 = h1 @ W2 + b2      -> g_h2 = relu(u2)
//   V  = (h1>0) @ Q        -> per-row partial:  sum_i (u2_i>0)*V_i  (64-col block)
// Tiles 64x64, BK=16, 256 threads, 4x4 per-thread per GEMM. grid (8, 16).
// Each (rowtile, colblock) writes a unique g_part slot: no atomics.
// ---------------------------------------------------------------------------
__global__ __launch_bounds__(256) void k2_layer2(const float* __restrict__ W2,
                                                 const float* __restrict__ b2) {
    __shared__ float As[16][64];
    __shared__ float Bs1[16][64];
    __shared__ float Bs2[16][64];
    __shared__ float red[16][64];

    int cb = blockIdx.x;                 // 0..7  -> cols col0..col0+63
    int rb = blockIdx.y;                 // 0..15 -> rows row0..row0+63
    int row0 = rb * 64, col0 = cb * 64;
    int t = threadIdx.x;
    int tx = t & 15, ty = t >> 4;

    float au[4][4], av[4][4];
#pragma unroll
    for (int r = 0; r < 4; ++r)
#pragma unroll
        for (int c = 0; c < 4; ++c) { au[r][c] = 0.f; av[r][c] = 0.f; }

    int ar = t >> 2, ak = (t & 3) * 4;   // A load: row ar (0..63), k off ak
    int bk = t >> 4, bc = (t & 15) * 4;  // B load: k row bk (0..15), col bc

    for (int k0 = 0; k0 < HID; k0 += 16) {
        float4 a4 = *(const float4*)&g_h1[(row0 + ar) * HID + k0 + ak];
        As[ak + 0][ar] = a4.x; As[ak + 1][ar] = a4.y;
        As[ak + 2][ar] = a4.z; As[ak + 3][ar] = a4.w;
        *(float4*)&Bs1[bk][bc] = *(const float4*)&W2[(k0 + bk) * HID + col0 + bc];
        *(float4*)&Bs2[bk][bc] = *(const float4*)&g_Q[(k0 + bk) * HID + col0 + bc];
        __syncthreads();

#pragma unroll
        for (int kk = 0; kk < 16; ++kk) {
            float a[4], m[4], w[4], q[4];
            *(float4*)a = *(const float4*)&As[kk][ty * 4];
            *(float4*)w = *(const float4*)&Bs1[kk][tx * 4];
            *(float4*)q = *(const float4*)&Bs2[kk][tx * 4];
#pragma unroll
            for (int r = 0; r < 4; ++r) m[r] = (a[r] > 0.f) ? 1.f : 0.f;
#pragma unroll
            for (int r = 0; r < 4; ++r)
#pragma unroll
                for (int c = 0; c < 4; ++c) {
                    au[r][c] += a[r] * w[c];
                    av[r][c] += m[r] * q[c];
                }
        }
        __syncthreads();
    }

    // epilogue: h2 = relu(u2), partial trace = sum_i (u2>0)*V
    float b2v[4];
    *(float4*)b2v = *(const float4*)&b2[col0 + tx * 4];
    float pr[4];
#pragma unroll
    for (int r = 0; r < 4; ++r) {
        float h2v[4];
        float s = 0.f;
#pragma unroll
        for (int c = 0; c < 4; ++c) {
            float u = au[r][c] + b2v[c];
            h2v[c] = fmaxf(u, 0.f);
            s += (u > 0.f) ? av[r][c] : 0.f;
        }
        *(float4*)&g_h2[(row0 + ty * 4 + r) * HID + col0 + tx * 4] = *(float4*)h2v;
        pr[r] = s;
    }
#pragma unroll
    for (int r = 0; r < 4; ++r) red[tx][ty * 4 + r] = pr[r];
    __syncthreads();
    if (t < 64) {
        float s = 0.f;
#pragma unroll
        for (int x = 0; x < 16; ++x) s += red[x][t];
        g_part[(row0 + t) * 8 + cb] = s;
    }
}

// ---------------------------------------------------------------------------
// K3: y_new = h2 @ W3 + b3;  trace = dt/H * sum_j(y_new - y_old) + dt * bilin;
//     log_det -= trace.
// grid: 64 blocks * 256 threads, 16 rows per block (4 rows per thread group).
// On the first (eval-0) pass, dolog=0 and y_old aliases y_new (diff=0, unused).
// ---------------------------------------------------------------------------
__global__ __launch_bounds__(256) void k3_layer3(const float* __restrict__ W3,
                                                 const float* __restrict__ b3,
                                                 float* __restrict__ out_logdet,
                                                 float dt, int newIdx, int dolog) {
    __shared__ float hs[16 * HID];
    __shared__ float sdiff[16][64];
    float* yn = g_y[newIdx];
    const float* yo = dolog ? g_y[newIdx ^ 1] : g_y[newIdx];

    int row0 = blockIdx.x * 16;
    int t = threadIdx.x;
#pragma unroll
    for (int q = 0; q < 32; ++q) {
        int idx = t + 256 * q;
        hs[idx] = g_h2[row0 * HID + idx];
    }
    __syncthreads();

    int j = t & 63, rg = t >> 6;         // 4 row-groups of 4 rows
    float acc[4] = {0.f, 0.f, 0.f, 0.f};
#pragma unroll 4
    for (int i = 0; i < HID; ++i) {
        float w = W3[i * DIM + j];
#pragma unroll
        for (int r = 0; r < 4; ++r)
            acc[r] += hs[(rg * 4 + r) * HID + i] * w;
    }
    float bj = b3[j];
#pragma unroll
    for (int r = 0; r < 4; ++r) {
        int row = rg * 4 + r;
        float y = acc[r] + bj;
        yn[(row0 + row) * DIM + j] = y;
        sdiff[row][j] = y - yo[(row0 + row) * DIM + j];
    }
    __syncthreads();

    if (dolog && t < 16) {
        float S = 0.f;
        for (int jj = 0; jj < 64; ++jj) S += sdiff[t][jj];
        float bs = 0.f;
#pragma unroll
        for (int cbk = 0; cbk < 8; ++cbk) bs += g_part[(row0 + t) * 8 + cbk];
        float trace = S * (dt / HSTEP) + bs * dt;
        out_logdet[row0 + t] -= trace;
    }
}

// final z copy into d_out
__global__ __launch_bounds__(256) void k_final(float* __restrict__ out) {
    int i = blockIdx.x * 256 + threadIdx.x;
    out[i] = g_z[i];
}

// ---------------------------------------------------------------------------
extern "C" void kernel_launch(void* const* d_in, const int* in_sizes, int n_in,
                              void* d_out, int out_size) {
    (void)in_sizes; (void)n_in; (void)out_size;
    const float* x  = (const float*)d_in[0];
    const float* W1 = (const float*)d_in[1];
    const float* b1 = (const float*)d_in[2];
    const float* W2 = (const float*)d_in[3];
    const float* b2 = (const float*)d_in[4];
    const float* W3 = (const float*)d_in[5];
    const float* b3 = (const float*)d_in[6];
    float* out        = (float*)d_out;
    float* out_logdet = out + BATCH * DIM;

    // dts matching fp32 linspace(0,1,10) diffs
    float tt[NSTEP + 1];
    for (int i = 0; i <= NSTEP; ++i) tt[i] = (float)i / 9.0f;

    dim3 g2(8, 16);

    k_init<<<512, 256>>>(W1, W2, W3, out_logdet);

    // eval 0 at z = x  (fills g_z, y buffer 0; no log_det update)
    k1_layer1<<<64, 256>>>(x, W1, b1, 0.f, 0, 1);
    k2_layer2<<<g2, 256>>>(W2, b2);
    k3_layer3<<<64, 256>>>(W3, b3, out_logdet, 0.f, 0, 0);

    // 9 Euler steps
    for (int s = 1; s <= NSTEP; ++s) {
        float dt = tt[s] - tt[s - 1];
        int newIdx = s & 1;
        int oldIdx = newIdx ^ 1;
        k1_layer1<<<64, 256>>>(x, W1, b1, dt, oldIdx, 0);  // z += dt*y_old; layer1 at z_new
        k2_layer2<<<g2, 256>>>(W2, b2);                    // layer2 + masked trace GEMM
        k3_layer3<<<64, 256>>>(W3, b3, out_logdet, dt, newIdx, 1);
    }

    k_final<<<256, 256>>>(out);
}

// round 9
// speedup vs baseline: 1.2703x; 1.2703x over previous
#include <cuda_runtime.h>

// ---------------------------------------------------------------------------
// NeuralODEFlow: z' = mlp(z), Euler, log_det via finite-difference trace.
// Key identity (mlp is piecewise linear in z):
//   trace_step = dt/H * sum_j (y_new_j - y_old_j)   [the "updated-z bug" term]
//              + dt * m1^T Q m2                      [exact masked Jacobian trace]
// with Q[k,i] = W2[k,i] * (W3@W1)[i,k], m1/m2 = ReLU masks at z_new.
// ---------------------------------------------------------------------------

#define BATCH 1024
#define DIM   64
#define HID   512
#define NSTEP 9
#define HSTEP 1e-5f

// scratch (device globals: allocation-free)
__device__ float g_Q[HID * HID];
__device__ float g_z[BATCH * DIM];
__device__ float g_h1[BATCH * HID];
__device__ float g_h2[BATCH * HID];
__device__ float g_y[2][BATCH * DIM];
__device__ float g_part[BATCH * 8];

// ---------------------------------------------------------------------------
// k_init: Q[k,i] = W2[k,i] * P[i,k], P = W3 @ W1  ([512,64]@[64,512]).
// Tiled GEMM: grid (8,8); block (bx,by) computes Q[k0:k0+64, i0:i0+64],
// i0 = bx*64, k0 = by*64. 256 threads, 4x4 per thread. Also zeros log_det.
// ---------------------------------------------------------------------------
__global__ __launch_bounds__(256) void k_init(const float* __restrict__ W1,
                                              const float* __restrict__ W2,
                                              const float* __restrict__ W3,
                                              float* __restrict__ out_logdet) {
    __shared__ float w3t[64][68];   // w3t[j][i] = W3[i0+i][j]  (padded, 16B-aligned rows)
    __shared__ float w1s[64][64];   // w1s[j][k] = W1[j][k0+k]
    int i0 = blockIdx.x * 64, k0 = blockIdx.y * 64;
    int t = threadIdx.x;

#pragma unroll
    for (int q = 0; q < 16; ++q) {
        int e = t + 256 * q;            // 0..4095
        int hi = e >> 6, lo = e & 63;
        w3t[lo][hi] = W3[(i0 + hi) * DIM + lo];        // coalesced global read
        w1s[hi][lo] = W1[hi * HID + k0 + lo];          // coalesced
    }
    __syncthreads();

    int tx = t & 15, ty = t >> 4;       // tx -> i group, ty -> k group
    float acc[4][4];
#pragma unroll
    for (int r = 0; r < 4; ++r)
#pragma unroll
        for (int c = 0; c < 4; ++c) acc[r][c] = 0.f;

#pragma unroll 4
    for (int j = 0; j < 64; ++j) {
        float a[4], b[4];
        *(float4*)a = *(const float4*)&w3t[j][tx * 4];   // i values
        *(float4*)b = *(const float4*)&w1s[j][ty * 4];   // k values
#pragma unroll
        for (int r = 0; r < 4; ++r)
#pragma unroll
            for (int c = 0; c < 4; ++c) acc[r][c] += b[r] * a[c];
    }

#pragma unroll
    for (int r = 0; r < 4; ++r) {
        int idx = (k0 + ty * 4 + r) * HID + i0 + tx * 4;
        float4 w2v = *(const float4*)&W2[idx];
        float4 qv;
        qv.x = w2v.x * acc[r][0];
        qv.y = w2v.y * acc[r][1];
        qv.z = w2v.z * acc[r][2];
        qv.w = w2v.w * acc[r][3];
        *(float4*)&g_Q[idx] = qv;
    }

    if (blockIdx.x == 0 && blockIdx.y == 0) {
        for (int i = t; i < BATCH; i += 256) out_logdet[i] = 0.f;
    }
}

// ---------------------------------------------------------------------------
// K1: z_new = (first ? x : z + dt*y_old);  h1 = relu(z_new @ W1 + b1)
// grid: 64 blocks * 256 threads, 16 rows per block.
// ---------------------------------------------------------------------------
__global__ __launch_bounds__(256) void k1_layer1(const float* __restrict__ xin,
                                                 const float* __restrict__ W1,
                                                 const float* __restrict__ b1,
                                                 float dt, int oldIdx, int first) {
    __shared__ float zs[16 * 64];
    const float* yo = g_y[oldIdx];
    int row0 = blockIdx.x * 16;
    int t = threadIdx.x;

#pragma unroll
    for (int q = 0; q < 4; ++q) {
        int idx = t + 256 * q;               // 0..1023 within block's 16x64
        int g = row0 * DIM + idx;
        float z = first ? xin[g] : (g_z[g] + dt * yo[g]);
        zs[idx] = z;
        g_z[g] = z;
    }
    __syncthreads();

    float acc0[16], acc1[16];
#pragma unroll
    for (int r = 0; r < 16; ++r) { acc0[r] = 0.f; acc1[r] = 0.f; }
    int c0 = t, c1 = t + 256;
#pragma unroll 4
    for (int k = 0; k < 64; ++k) {
        float wa = W1[k * HID + c0];
        float wb = W1[k * HID + c1];
#pragma unroll
        for (int r = 0; r < 16; ++r) {
            float z = zs[r * 64 + k];
            acc0[r] += z * wa;
            acc1[r] += z * wb;
        }
    }
    float ba = b1[c0], bb = b1[c1];
#pragma unroll
    for (int r = 0; r < 16; ++r) {
        g_h1[(row0 + r) * HID + c0] = fmaxf(acc0[r] + ba, 0.f);
        g_h1[(row0 + r) * HID + c1] = fmaxf(acc1[r] + bb, 0.f);
    }
}

// ---------------------------------------------------------------------------
// K2: fused dual GEMM over A = h1 [1024x512]:
//   u2 = h1 @ W2 + b2      -> g_h2 = relu(u2)
//   V  = (h1>0) @ Q        -> per-row partial:  sum_i (u2_i>0)*V_i  (64-col block)
// Tiles 64x64, BK=16, 256 threads, 4x4 per-thread per GEMM. grid (8, 16).
// Each (rowtile, colblock) writes a unique g_part slot: no atomics.
// (FFMA-floor bound at ~36 TF/s fp32 — unchanged this round.)
// ---------------------------------------------------------------------------
__global__ __launch_bounds__(256) void k2_layer2(const float* __restrict__ W2,
                                                 const float* __restrict__ b2) {
    __shared__ float As[16][64];
    __shared__ float Bs1[16][64];
    __shared__ float Bs2[16][64];
    __shared__ float red[16][64];

    int cb = blockIdx.x;                 // 0..7  -> cols col0..col0+63
    int rb = blockIdx.y;                 // 0..15 -> rows row0..row0+63
    int row0 = rb * 64, col0 = cb * 64;
    int t = threadIdx.x;
    int tx = t & 15, ty = t >> 4;

    float au[4][4], av[4][4];
#pragma unroll
    for (int r = 0; r < 4; ++r)
#pragma unroll
        for (int c = 0; c < 4; ++c) { au[r][c] = 0.f; av[r][c] = 0.f; }

    int ar = t >> 2, ak = (t & 3) * 4;   // A load: row ar (0..63), k off ak
    int bk = t >> 4, bc = (t & 15) * 4;  // B load: k row bk (0..15), col bc

    for (int k0 = 0; k0 < HID; k0 += 16) {
        float4 a4 = *(const float4*)&g_h1[(row0 + ar) * HID + k0 + ak];
        As[ak + 0][ar] = a4.x; As[ak + 1][ar] = a4.y;
        As[ak + 2][ar] = a4.z; As[ak + 3][ar] = a4.w;
        *(float4*)&Bs1[bk][bc] = *(const float4*)&W2[(k0 + bk) * HID + col0 + bc];
        *(float4*)&Bs2[bk][bc] = *(const float4*)&g_Q[(k0 + bk) * HID + col0 + bc];
        __syncthreads();

#pragma unroll
        for (int kk = 0; kk < 16; ++kk) {
            float a[4], m[4], w[4], q[4];
            *(float4*)a = *(const float4*)&As[kk][ty * 4];
            *(float4*)w = *(const float4*)&Bs1[kk][tx * 4];
            *(float4*)q = *(const float4*)&Bs2[kk][tx * 4];
#pragma unroll
            for (int r = 0; r < 4; ++r) m[r] = (a[r] > 0.f) ? 1.f : 0.f;
#pragma unroll
            for (int r = 0; r < 4; ++r)
#pragma unroll
                for (int c = 0; c < 4; ++c) {
                    au[r][c] += a[r] * w[c];
                    av[r][c] += m[r] * q[c];
                }
        }
        __syncthreads();
    }

    // epilogue: h2 = relu(u2), partial trace = sum_i (u2>0)*V
    float b2v[4];
    *(float4*)b2v = *(const float4*)&b2[col0 + tx * 4];
    float pr[4];
#pragma unroll
    for (int r = 0; r < 4; ++r) {
        float h2v[4];
        float s = 0.f;
#pragma unroll
        for (int c = 0; c < 4; ++c) {
            float u = au[r][c] + b2v[c];
            h2v[c] = fmaxf(u, 0.f);
            s += (u > 0.f) ? av[r][c] : 0.f;
        }
        *(float4*)&g_h2[(row0 + ty * 4 + r) * HID + col0 + tx * 4] = *(float4*)h2v;
        pr[r] = s;
    }
#pragma unroll
    for (int r = 0; r < 4; ++r) red[tx][ty * 4 + r] = pr[r];
    __syncthreads();
    if (t < 64) {
        float s = 0.f;
#pragma unroll
        for (int x = 0; x < 16; ++x) s += red[x][t];
        g_part[(row0 + t) * 8 + cb] = s;
    }
}

// ---------------------------------------------------------------------------
// K3 (rewritten): y_new = h2 @ W3 + b3;
//   trace = dt/H * sum_j(y_new - y_old) + dt * bilin;  log_det -= trace.
// grid: 128 blocks * 256 threads, 8 rows per block, 2 rows per thread.
// W3 (128KB) is L1-resident; hs reads are warp-broadcast LDS.
// Summation orders match the previous (validated) kernel.
// ---------------------------------------------------------------------------
__global__ __launch_bounds__(256) void k3_layer3(const float* __restrict__ W3,
                                                 const float* __restrict__ b3,
                                                 float* __restrict__ out_logdet,
                                                 float dt, int newIdx, int dolog) {
    __shared__ float hs[8 * HID];        // 16KB
    __shared__ float sdiff[8][64];
    float* yn = g_y[newIdx];
    const float* yo = dolog ? g_y[newIdx ^ 1] : g_y[newIdx];

    int row0 = blockIdx.x * 8;
    int t = threadIdx.x;

    // vectorized fill: 8*512 floats = 1024 float4, 4 per thread
    const float4* src = (const float4*)&g_h2[row0 * HID];
    float4* dst = (float4*)hs;
#pragma unroll
    for (int q = 0; q < 4; ++q) dst[t + 256 * q] = src[t + 256 * q];
    __syncthreads();

    int j = t & 63, rg = t >> 6;         // thread handles rows rg and rg+4
    float acc0 = 0.f, acc1 = 0.f;
#pragma unroll 8
    for (int i = 0; i < HID; ++i) {
        float w = W3[i * DIM + j];
        acc0 += hs[rg * HID + i] * w;          // warp-broadcast LDS
        acc1 += hs[(rg + 4) * HID + i] * w;
    }
    float bj = b3[j];
    float y0 = acc0 + bj, y1 = acc1 + bj;
    int r0 = row0 + rg, r1 = row0 + rg + 4;
    yn[r0 * DIM + j] = y0;
    yn[r1 * DIM + j] = y1;
    sdiff[rg][j]     = y0 - yo[r0 * DIM + j];
    sdiff[rg + 4][j] = y1 - yo[r1 * DIM + j];
    __syncthreads();

    if (dolog && t < 8) {
        float S = 0.f;
        for (int jj = 0; jj < 64; ++jj) S += sdiff[t][jj];
        float bs = 0.f;
#pragma unroll
        for (int cbk = 0; cbk < 8; ++cbk) bs += g_part[(row0 + t) * 8 + cbk];
        float trace = S * (dt / HSTEP) + bs * dt;
        out_logdet[row0 + t] -= trace;
    }
}

// final z copy into d_out
__global__ __launch_bounds__(256) void k_final(float* __restrict__ out) {
    int i = blockIdx.x * 256 + threadIdx.x;
    out[i] = g_z[i];
}

// ---------------------------------------------------------------------------
extern "C" void kernel_launch(void* const* d_in, const int* in_sizes, int n_in,
                              void* d_out, int out_size) {
    (void)in_sizes; (void)n_in; (void)out_size;
    const float* x  = (const float*)d_in[0];
    const float* W1 = (const float*)d_in[1];
    const float* b1 = (const float*)d_in[2];
    const float* W2 = (const float*)d_in[3];
    const float* b2 = (const float*)d_in[4];
    const float* W3 = (const float*)d_in[5];
    const float* b3 = (const float*)d_in[6];
    float* out        = (float*)d_out;
    float* out_logdet = out + BATCH * DIM;

    // dts matching fp32 linspace(0,1,10) diffs
    float tt[NSTEP + 1];
    for (int i = 0; i <= NSTEP; ++i) tt[i] = (float)i / 9.0f;

    dim3 g2(8, 16);
    dim3 gi(8, 8);

    k_init<<<gi, 256>>>(W1, W2, W3, out_logdet);

    // eval 0 at z = x  (fills g_z, y buffer 0; no log_det update)
    k1_layer1<<<64, 256>>>(x, W1, b1, 0.f, 0, 1);
    k2_layer2<<<g2, 256>>>(W2, b2);
    k3_layer3<<<128, 256>>>(W3, b3, out_logdet, 0.f, 0, 0);

    // 9 Euler steps
    for (int s = 1; s <= NSTEP; ++s) {
        float dt = tt[s] - tt[s - 1];
        int newIdx = s & 1;
        int oldIdx = newIdx ^ 1;
        k1_layer1<<<64, 256>>>(x, W1, b1, dt, oldIdx, 0);  // z += dt*y_old; layer1 at z_new
        k2_layer2<<<g2, 256>>>(W2, b2);                    // layer2 + masked trace GEMM
        k3_layer3<<<128, 256>>>(W3, b3, out_logdet, dt, newIdx, 1);
    }

    k_final<<<256, 256>>>(out);
}

// round 10
// speedup vs baseline: 1.5082x; 1.1873x over previous
#include <cuda_runtime.h>

// ---------------------------------------------------------------------------
// NeuralODEFlow: z' = mlp(z), Euler, log_det via finite-difference trace.
// Key identity (mlp is piecewise linear in z):
//   trace_step = dt/H * sum_j (y_new_j - y_old_j)   [the "updated-z bug" term]
//              + dt * m1^T Q m2                      [exact masked Jacobian trace]
// with Q[k,i] = W2[k,i] * (W3@W1)[i,k], m1/m2 = ReLU masks at z_new.
//
// R9: layer-3 GEMM fused into k2's epilogue as per-colblock y-partials
// (64x64x64 per CTA, +3% FMA); k3 becomes a tiny reduce kernel. g_h2 gone.
// ---------------------------------------------------------------------------

#define BATCH 1024
#define DIM   64
#define HID   512
#define NSTEP 9
#define HSTEP 1e-5f

// scratch (device globals: allocation-free)
__device__ float g_Q[HID * HID];
__device__ float g_z[BATCH * DIM];
__device__ float g_h1[BATCH * HID];
__device__ float g_ypart[BATCH * 8 * DIM];   // [row][cb][j]
__device__ float g_y[2][BATCH * DIM];
__device__ float g_part[BATCH * 8];

// ---------------------------------------------------------------------------
// k_init: Q[k,i] = W2[k,i] * P[i,k], P = W3 @ W1. grid (8,8), 256 thr.
// ---------------------------------------------------------------------------
__global__ __launch_bounds__(256) void k_init(const float* __restrict__ W1,
                                              const float* __restrict__ W2,
                                              const float* __restrict__ W3,
                                              float* __restrict__ out_logdet) {
    __shared__ float w3t[64][68];   // w3t[j][i] = W3[i0+i][j]
    __shared__ float w1s[64][64];   // w1s[j][k] = W1[j][k0+k]
    int i0 = blockIdx.x * 64, k0 = blockIdx.y * 64;
    int t = threadIdx.x;

#pragma unroll
    for (int q = 0; q < 16; ++q) {
        int e = t + 256 * q;
        int hi = e >> 6, lo = e & 63;
        w3t[lo][hi] = W3[(i0 + hi) * DIM + lo];
        w1s[hi][lo] = W1[hi * HID + k0 + lo];
    }
    __syncthreads();

    int tx = t & 15, ty = t >> 4;
    float acc[4][4];
#pragma unroll
    for (int r = 0; r < 4; ++r)
#pragma unroll
        for (int c = 0; c < 4; ++c) acc[r][c] = 0.f;

#pragma unroll 4
    for (int j = 0; j < 64; ++j) {
        float a[4], b[4];
        *(float4*)a = *(const float4*)&w3t[j][tx * 4];
        *(float4*)b = *(const float4*)&w1s[j][ty * 4];
#pragma unroll
        for (int r = 0; r < 4; ++r)
#pragma unroll
            for (int c = 0; c < 4; ++c) acc[r][c] += b[r] * a[c];
    }

#pragma unroll
    for (int r = 0; r < 4; ++r) {
        int idx = (k0 + ty * 4 + r) * HID + i0 + tx * 4;
        float4 w2v = *(const float4*)&W2[idx];
        float4 qv;
        qv.x = w2v.x * acc[r][0];
        qv.y = w2v.y * acc[r][1];
        qv.z = w2v.z * acc[r][2];
        qv.w = w2v.w * acc[r][3];
        *(float4*)&g_Q[idx] = qv;
    }

    if (blockIdx.x == 0 && blockIdx.y == 0) {
        for (int i = t; i < BATCH; i += 256) out_logdet[i] = 0.f;
    }
}

// ---------------------------------------------------------------------------
// K1: z_new = (first ? x : z + dt*y_old);  h1 = relu(z_new @ W1 + b1)
// grid: 64 blocks * 256 threads, 16 rows per block.
// ---------------------------------------------------------------------------
__global__ __launch_bounds__(256) void k1_layer1(const float* __restrict__ xin,
                                                 const float* __restrict__ W1,
                                                 const float* __restrict__ b1,
                                                 float dt, int oldIdx, int first) {
    __shared__ float zs[16 * 64];
    const float* yo = g_y[oldIdx];
    int row0 = blockIdx.x * 16;
    int t = threadIdx.x;

#pragma unroll
    for (int q = 0; q < 4; ++q) {
        int idx = t + 256 * q;
        int g = row0 * DIM + idx;
        float z = first ? xin[g] : (g_z[g] + dt * yo[g]);
        zs[idx] = z;
        g_z[g] = z;
    }
    __syncthreads();

    float acc0[16], acc1[16];
#pragma unroll
    for (int r = 0; r < 16; ++r) { acc0[r] = 0.f; acc1[r] = 0.f; }
    int c0 = t, c1 = t + 256;
#pragma unroll 4
    for (int k = 0; k < 64; ++k) {
        float wa = W1[k * HID + c0];
        float wb = W1[k * HID + c1];
#pragma unroll
        for (int r = 0; r < 16; ++r) {
            float z = zs[r * 64 + k];
            acc0[r] += z * wa;
            acc1[r] += z * wb;
        }
    }
    float ba = b1[c0], bb = b1[c1];
#pragma unroll
    for (int r = 0; r < 16; ++r) {
        g_h1[(row0 + r) * HID + c0] = fmaxf(acc0[r] + ba, 0.f);
        g_h1[(row0 + r) * HID + c1] = fmaxf(acc1[r] + bb, 0.f);
    }
}

// ---------------------------------------------------------------------------
// K2: fused triple GEMM over A = h1 [1024x512], tile 64x64, BK=16, grid (8,16):
//   u2   = h1 @ W2 + b2       (mainloop)
//   V    = (h1>0) @ Q         (mainloop; trace partial in epilogue)
//   ypart= relu(u2) @ W3[col0:col0+64,:]   (epilogue, 64x64x64 from smem)
// Shared memory unioned: mainloop As/Bs1/Bs2 reuse epilogue h2s region.
// ---------------------------------------------------------------------------
#define H2S(r_, c_)  sm[(r_) * 68 + (c_)]
#define W3S(k_, j_)  sm[4352 + (k_) * 68 + (j_)]
#define RED(x_, y_)  sm[8704 + (x_) * 64 + (y_)]
#define ASM(k_, r_)  sm[(k_) * 64 + (r_)]
#define BS1(k_, c_)  sm[1024 + (k_) * 64 + (c_)]
#define BS2(k_, c_)  sm[2048 + (k_) * 64 + (c_)]

__global__ __launch_bounds__(256) void k2_layer2(const float* __restrict__ W2,
                                                 const float* __restrict__ b2,
                                                 const float* __restrict__ W3) {
    __shared__ float sm[8704 + 16 * 64];     // 38.9 KB

    int cb = blockIdx.x;                 // 0..7
    int rb = blockIdx.y;                 // 0..15
    int row0 = rb * 64, col0 = cb * 64;
    int t = threadIdx.x;
    int tx = t & 15, ty = t >> 4;

    float au[4][4], av[4][4];
#pragma unroll
    for (int r = 0; r < 4; ++r)
#pragma unroll
        for (int c = 0; c < 4; ++c) { au[r][c] = 0.f; av[r][c] = 0.f; }

    int ar = t >> 2, ak = (t & 3) * 4;
    int bk = t >> 4, bc = (t & 15) * 4;

    for (int k0 = 0; k0 < HID; k0 += 16) {
        float4 a4 = *(const float4*)&g_h1[(row0 + ar) * HID + k0 + ak];
        ASM(ak + 0, ar) = a4.x; ASM(ak + 1, ar) = a4.y;
        ASM(ak + 2, ar) = a4.z; ASM(ak + 3, ar) = a4.w;
        *(float4*)&BS1(bk, bc) = *(const float4*)&W2[(k0 + bk) * HID + col0 + bc];
        *(float4*)&BS2(bk, bc) = *(const float4*)&g_Q[(k0 + bk) * HID + col0 + bc];
        __syncthreads();

#pragma unroll
        for (int kk = 0; kk < 16; ++kk) {
            float a[4], m[4], w[4], q[4];
            *(float4*)a = *(const float4*)&ASM(kk, ty * 4);
            *(float4*)w = *(const float4*)&BS1(kk, tx * 4);
            *(float4*)q = *(const float4*)&BS2(kk, tx * 4);
#pragma unroll
            for (int r = 0; r < 4; ++r) m[r] = (a[r] > 0.f) ? 1.f : 0.f;
#pragma unroll
            for (int r = 0; r < 4; ++r)
#pragma unroll
                for (int c = 0; c < 4; ++c) {
                    au[r][c] += a[r] * w[c];
                    av[r][c] += m[r] * q[c];
                }
        }
        __syncthreads();
    }

    // ---- epilogue phase 1: h2 tile -> smem, trace partial -> red, W3 tile -> smem
    float b2v[4];
    *(float4*)b2v = *(const float4*)&b2[col0 + tx * 4];
#pragma unroll
    for (int r = 0; r < 4; ++r) {
        float h2v[4];
        float s = 0.f;
#pragma unroll
        for (int c = 0; c < 4; ++c) {
            float u = au[r][c] + b2v[c];
            h2v[c] = fmaxf(u, 0.f);
            s += (u > 0.f) ? av[r][c] : 0.f;
        }
        *(float4*)&H2S(ty * 4 + r, tx * 4) = *(float4*)h2v;
        RED(tx, ty * 4 + r) = s;
    }
    // cooperative coalesced load of W3[col0:col0+64][0:64]
#pragma unroll
    for (int q = 0; q < 4; ++q) {
        int f = t + 256 * q;              // float4 index 0..1023
        int k = f >> 4, j4 = (f & 15) * 4;
        *(float4*)&W3S(k, j4) = *(const float4*)&W3[(col0 + k) * DIM + j4];
    }
    __syncthreads();

    // ---- epilogue phase 2: ypart[row][cb][j] = h2_tile @ W3_tile
    float ay[4][4];
#pragma unroll
    for (int r = 0; r < 4; ++r)
#pragma unroll
        for (int c = 0; c < 4; ++c) ay[r][c] = 0.f;

#pragma unroll 8
    for (int k = 0; k < 64; ++k) {
        float a[4], w[4];
#pragma unroll
        for (int r = 0; r < 4; ++r) a[r] = H2S(ty * 4 + r, k);
        *(float4*)w = *(const float4*)&W3S(k, tx * 4);
#pragma unroll
        for (int r = 0; r < 4; ++r)
#pragma unroll
            for (int c = 0; c < 4; ++c) ay[r][c] += a[r] * w[c];
    }
#pragma unroll
    for (int r = 0; r < 4; ++r) {
        int row = row0 + ty * 4 + r;
        *(float4*)&g_ypart[(row * 8 + cb) * DIM + tx * 4] = *(float4*)ay[r];
    }

    // ---- trace partial reduction (unique slot per (rowtile, cb): no atomics)
    if (t < 64) {
        float s = 0.f;
#pragma unroll
        for (int x = 0; x < 16; ++x) s += RED(x, t);
        g_part[(row0 + t) * 8 + cb] = s;
    }
}

// ---------------------------------------------------------------------------
// K3r (reduce): y = sum_cb ypart + b3;  trace = dt/H*sum_j(y-y_old) + dt*bilin;
// grid: 64 blocks * 256 threads, 16 rows per block, 4 rows per thread.
// ---------------------------------------------------------------------------
__global__ __launch_bounds__(256) void k3_reduce(const float* __restrict__ b3,
                                                 float* __restrict__ out_logdet,
                                                 float dt, int newIdx, int dolog) {
    __shared__ float sdiff[16][64];
    float* yn = g_y[newIdx];
    const float* yo = dolog ? g_y[newIdx ^ 1] : g_y[newIdx];

    int row0 = blockIdx.x * 16;
    int t = threadIdx.x;
    int j = t & 63, rq = t >> 6;         // rows rq, rq+4, rq+8, rq+12

    float bj = b3[j];
    float v[4][8];
#pragma unroll
    for (int m = 0; m < 4; ++m) {
        int row = row0 + rq + m * 4;
#pragma unroll
        for (int cb = 0; cb < 8; ++cb)
            v[m][cb] = g_ypart[(row * 8 + cb) * DIM + j];
    }
#pragma unroll
    for (int m = 0; m < 4; ++m) {
        int lr = rq + m * 4;
        int row = row0 + lr;
        float acc = bj;
#pragma unroll
        for (int cb = 0; cb < 8; ++cb) acc += v[m][cb];
        yn[row * DIM + j] = acc;
        sdiff[lr][j] = acc - yo[row * DIM + j];
    }
    __syncthreads();

    if (dolog && t < 16) {
        float S = 0.f;
        for (int jj = 0; jj < 64; ++jj) S += sdiff[t][jj];
        float bs = 0.f;
#pragma unroll
        for (int cbk = 0; cbk < 8; ++cbk) bs += g_part[(row0 + t) * 8 + cbk];
        float trace = S * (dt / HSTEP) + bs * dt;
        out_logdet[row0 + t] -= trace;
    }
}

// final z copy into d_out
__global__ __launch_bounds__(256) void k_final(float* __restrict__ out) {
    int i = blockIdx.x * 256 + threadIdx.x;
    out[i] = g_z[i];
}

// ---------------------------------------------------------------------------
extern "C" void kernel_launch(void* const* d_in, const int* in_sizes, int n_in,
                              void* d_out, int out_size) {
    (void)in_sizes; (void)n_in; (void)out_size;
    const float* x  = (const float*)d_in[0];
    const float* W1 = (const float*)d_in[1];
    const float* b1 = (const float*)d_in[2];
    const float* W2 = (const float*)d_in[3];
    const float* b2 = (const float*)d_in[4];
    const float* W3 = (const float*)d_in[5];
    const float* b3 = (const float*)d_in[6];
    float* out        = (float*)d_out;
    float* out_logdet = out + BATCH * DIM;

    float tt[NSTEP + 1];
    for (int i = 0; i <= NSTEP; ++i) tt[i] = (float)i / 9.0f;

    dim3 g2(8, 16);
    dim3 gi(8, 8);

    k_init<<<gi, 256>>>(W1, W2, W3, out_logdet);

    // eval 0 at z = x (fills g_z, y buffer 0; no log_det update)
    k1_layer1<<<64, 256>>>(x, W1, b1, 0.f, 0, 1);
    k2_layer2<<<g2, 256>>>(W2, b2, W3);
    k3_reduce<<<64, 256>>>(b3, out_logdet, 0.f, 0, 0);

    // 9 Euler steps
    for (int s = 1; s <= NSTEP; ++s) {
        float dt = tt[s] - tt[s - 1];
        int newIdx = s & 1;
        int oldIdx = newIdx ^ 1;
        k1_layer1<<<64, 256>>>(x, W1, b1, dt, oldIdx, 0);
        k2_layer2<<<g2, 256>>>(W2, b2, W3);
        k3_reduce<<<64, 256>>>(b3, out_logdet, dt, newIdx, 1);
    }

    k_final<<<256, 256>>>(out);
}